// round 14
// baseline (speedup 1.0000x reference)
#include <cuda_runtime.h>
#include <cuda_bf16.h>
#include <cstdint>

#define NTHR 256
#define TMR  32

// Weight blob (k16 layout): per layer 32 k16-chunks x [hl][n][pos].
// word(l, kt, hl, n, pos) at (l*32+kt)*8192 + hl*4096 + n*8 + pos,
// pos = 2*(kpl&3) + (kpl>>2) for k-pair kpl (0..7): B-fragment pair (kpl, kpl+4)
// is one contiguous 8B load: uint2 at  nt*64 + (lane>>2)*8 + 2*(lane&3).
__device__ __align__(16) uint32_t gW[6u * 262144u];   // 6 MB

// ---- smem byte offsets ----
#define SM_ACT_HI 0         // 8192 words (32 rows x 512 cols bf16-pairs)
#define SM_ACT_LO 32768     // 8192 words
#define SM_WBUF   65536     // 48 KB = 3 x 16KB plane ring
#define SM_TOTAL  114688    // 112 KB -> 2 CTAs/SM
// overlays inside WBUF (used only when the weight ring is dead):
#define SM_XIN    SM_WBUF             // layer0 input staging (768 B)
#define SM_L0W    (SM_WBUF + 1024)    // layer0 W_in (<=12 KB)
#define SM_L0B    (SM_WBUF + 16384)   // layer0 bias (2 KB)
#define SM_L0LW   (SM_WBUF + 18432)   // layer0 ln_w (2 KB)
#define SM_L0LB   (SM_WBUF + 20480)   // layer0 ln_b (2 KB)
#define SM_RED    SM_WBUF             // epilogue row stats (2 KB)
#define SM_OUTACC (SM_WBUF + 2048)    // LAST epilogue partials (3 KB)

__device__ __forceinline__ void cp16(void* dst, const void* src) {
    unsigned s = (unsigned)__cvta_generic_to_shared(dst);
    asm volatile("cp.async.cg.shared.global [%0], [%1], 16;" :: "r"(s), "l"(src));
}
__device__ __forceinline__ void cp_commit() { asm volatile("cp.async.commit_group;"); }
__device__ __forceinline__ void cp_wait0()  { asm volatile("cp.async.wait_group 0;"); }
__device__ __forceinline__ void cp_wait1()  { asm volatile("cp.async.wait_group 1;"); }

__device__ __forceinline__ void mma_k16(float* d,
                                        uint32_t a0, uint32_t a1, uint32_t a2, uint32_t a3,
                                        uint32_t b0, uint32_t b1) {
    asm volatile("mma.sync.aligned.m16n8k16.row.col.f32.bf16.bf16.f32 "
        "{%0,%1,%2,%3}, {%4,%5,%6,%7}, {%8,%9}, {%0,%1,%2,%3};"
        : "+f"(d[0]), "+f"(d[1]), "+f"(d[2]), "+f"(d[3])
        : "r"(a0), "r"(a1), "r"(a2), "r"(a3), "r"(b0), "r"(b1));
}

__device__ __forceinline__ uint32_t pack_split(float a, float b, uint32_t& lo) {
    __nv_bfloat16 ha = __float2bfloat16(a), hb = __float2bfloat16(b);
    __nv_bfloat16 la = __float2bfloat16(a - __bfloat162float(ha));
    __nv_bfloat16 lb = __float2bfloat16(b - __bfloat162float(hb));
    lo = (uint32_t)__bfloat16_as_ushort(la) | ((uint32_t)__bfloat16_as_ushort(lb) << 16);
    return (uint32_t)__bfloat16_as_ushort(ha) | ((uint32_t)__bfloat16_as_ushort(hb) << 16);
}

template<int F>
__host__ __device__ constexpr int hdim(int l) {
    return (F == 0) ? 256 : ((F == 2) ? 512 : ((l % 2 == 0) ? 512 : 256));
}

// ---------------- prep: split fp32 weights into hi/lo bf16 blob (k16 layout) ----
__global__ void split_weights(const float* __restrict__ Ws) {
    int id = blockIdx.x * 256 + threadIdx.x;        // 6*512*256 k-pairs
    int l  = id / (512 * 256);
    int r  = id - l * (512 * 256);
    int n  = r >> 8;
    int kp = r & 255;
    const float* W = Ws + ((size_t)l * 512 + n) * 512;
    float w0 = W[2 * kp], w1 = W[2 * kp + 1];
    __nv_bfloat16 h0 = __float2bfloat16(w0), h1 = __float2bfloat16(w1);
    __nv_bfloat16 l0 = __float2bfloat16(w0 - __bfloat162float(h0));
    __nv_bfloat16 l1 = __float2bfloat16(w1 - __bfloat162float(h1));
    int kt = kp >> 3, kpl = kp & 7;
    int pos = 2 * (kpl & 3) + (kpl >> 2);
    uint32_t base = (uint32_t)((l * 32 + kt) * 2) * 4096u + (uint32_t)(n * 8 + pos);
    gW[base]        = (uint32_t)__bfloat16_as_ushort(h0) | ((uint32_t)__bfloat16_as_ushort(h1) << 16);
    gW[base + 4096] = (uint32_t)__bfloat16_as_ushort(l0) | ((uint32_t)__bfloat16_as_ushort(l1) << 16);
}

// ---------------- layer 0 (K = 6) ----------------
template<int HOUT>
__device__ __noinline__ void layer0(uint8_t* sm,
    const float* __restrict__ inputs, const float* __restrict__ W_in,
    const float* __restrict__ b_in, const float* __restrict__ lnw,
    const float* __restrict__ lnb, int rowbase)
{
    uint32_t* actHi = (uint32_t*)(sm + SM_ACT_HI);
    uint32_t* actLo = (uint32_t*)(sm + SM_ACT_LO);
    float* xin   = (float*)(sm + SM_XIN);
    float* sW    = (float*)(sm + SM_L0W);
    float* sBias = (float*)(sm + SM_L0B);
    float* sLw   = (float*)(sm + SM_L0LW);
    float* sLb   = (float*)(sm + SM_L0LB);
    const int tid = threadIdx.x;

    for (int i = tid; i < HOUT * 6; i += NTHR) sW[i] = W_in[i];
    for (int i = tid; i < HOUT; i += NTHR) { sBias[i] = b_in[i]; sLw[i] = lnw[i]; sLb[i] = lnb[i]; }
    for (int i = tid; i < TMR * 6; i += NTHR) xin[i] = inputs[rowbase * 6 + i];
    __syncthreads();

    const int row = tid >> 3, sub = (tid >> 2) & 1, cp = tid & 3;
    float x[6];
    #pragma unroll
    for (int k = 0; k < 6; ++k) x[k] = xin[row * 6 + k];

    float s = 0.f, q = 0.f;
    for (int nt = sub; nt < HOUT / 8; nt += 2) {
        #pragma unroll
        for (int e = 0; e < 2; ++e) {
            int col = 8 * nt + 2 * cp + e;
            const float* w = sW + col * 6;
            float v = sBias[col];
            #pragma unroll
            for (int k = 0; k < 6; ++k) v += x[k] * w[k];
            s += v; q += v * v;
        }
    }
    #pragma unroll
    for (int o = 1; o <= 4; o <<= 1) {
        s += __shfl_xor_sync(0xffffffffu, s, o);
        q += __shfl_xor_sync(0xffffffffu, q, o);
    }
    const float mean = s * (1.0f / HOUT);
    const float rstd = rsqrtf(q * (1.0f / HOUT) - mean * mean + 1e-5f);

    for (int nt = sub; nt < HOUT / 8; nt += 2) {
        float y[2];
        #pragma unroll
        for (int e = 0; e < 2; ++e) {
            int col = 8 * nt + 2 * cp + e;
            const float* w = sW + col * 6;
            float v = sBias[col];
            #pragma unroll
            for (int k = 0; k < 6; ++k) v += x[k] * w[k];
            y[e] = fmaxf((v - mean) * rstd * sLw[col] + sLb[col], 0.f);
        }
        uint32_t lo;
        uint32_t hi = pack_split(y[0], y[1], lo);
        uint32_t idx = (uint32_t)(nt * TMR + row) * 4u + (uint32_t)cp;
        actHi[idx] = hi; actLo[idx] = lo;
    }
    __syncthreads();
}

// ---- mid layer: k16 HMMA 3-split GEMM, 3-stage plane ring, warp = 32r x HOUT/8c ----
template<int HIN, int HOUT, bool LAST>
__device__ __noinline__ void mid_layer(uint8_t* sm, int lane, int w,
    int lidx, int fidx,
    const float* __restrict__ bias, const float* __restrict__ lnw,
    const float* __restrict__ lnb, const float* __restrict__ W_out,
    const float* __restrict__ b_out, float* __restrict__ out, int rowbase)
{
    constexpr int KT  = HIN / 16;          // k16 chunks
    constexpr int NU  = 2 * KT;            // plane units
    constexpr int NT  = HOUT / 64;         // n8-tiles per warp
    constexpr int PW  = HOUT * 8;          // words per plane
    constexpr int NC4 = PW / 4 / NTHR;     // uint4 copies per thread per plane

    uint32_t* actHi = (uint32_t*)(sm + SM_ACT_HI);
    uint32_t* actLo = (uint32_t*)(sm + SM_ACT_LO);
    uint32_t* wbuf  = (uint32_t*)(sm + SM_WBUF);
    float* red    = (float*)(sm + SM_RED);
    float* outAcc = (float*)(sm + SM_OUTACC);
    const int tid = threadIdx.x;

    const uint32_t* wsrc = gW + (uint32_t)lidx * 262144u;
    auto stage = [&](int u) {
        const uint32_t* src = wsrc + (uint32_t)(u >> 1) * 8192u + (uint32_t)(u & 1) * 4096u;
        uint32_t* dst = wbuf + (u % 3) * PW;
        #pragma unroll
        for (int t = 0; t < NC4; ++t) {
            int v = (tid + t * NTHR) * 4;
            cp16(dst + v, src + v);
        }
    };

    float acc[2][NT][4];
    #pragma unroll
    for (int mb = 0; mb < 2; ++mb)
        #pragma unroll
        for (int t = 0; t < NT; ++t)
            acc[mb][t][0] = acc[mb][t][1] = acc[mb][t][2] = acc[mb][t][3] = 0.f;

    const int r  = lane >> 2;
    const int cp = lane & 3;
    const int ntb = w * NT;
    const uint32_t boff = (uint32_t)(r * 8 + 2 * cp);
    uint32_t ah[2][4];   // hi A-frags persist from hi-unit to lo-unit

    stage(0); cp_commit();
    if (NU > 1) { stage(1); cp_commit(); }

    for (int u = 0; u < NU; ++u) {
        if (u + 1 < NU) cp_wait1(); else cp_wait0();
        __syncthreads();
        if (u + 2 < NU) { stage(u + 2); cp_commit(); }

        const uint32_t* B = wbuf + (u % 3) * PW;
        const int kt = u >> 1;

        if ((u & 1) == 0) {
            uint32_t al[2][4];
            #pragma unroll
            for (int mb = 0; mb < 2; ++mb) {
                uint32_t i0 = (uint32_t)((2 * kt) * TMR + mb * 16 + r) * 4u + cp;
                uint32_t i2 = (uint32_t)((2 * kt + 1) * TMR + mb * 16 + r) * 4u + cp;
                ah[mb][0] = actHi[i0]; ah[mb][1] = actHi[i0 + 32];
                ah[mb][2] = actHi[i2]; ah[mb][3] = actHi[i2 + 32];
                al[mb][0] = actLo[i0]; al[mb][1] = actLo[i0 + 32];
                al[mb][2] = actLo[i2]; al[mb][3] = actLo[i2 + 32];
            }
            #pragma unroll
            for (int t = 0; t < NT; ++t) {
                uint2 bh = *(const uint2*)(B + (uint32_t)(ntb + t) * 64u + boff);
                #pragma unroll
                for (int mb = 0; mb < 2; ++mb) {
                    mma_k16(acc[mb][t], ah[mb][0], ah[mb][1], ah[mb][2], ah[mb][3], bh.x, bh.y);
                    mma_k16(acc[mb][t], al[mb][0], al[mb][1], al[mb][2], al[mb][3], bh.x, bh.y);
                }
            }
        } else {
            #pragma unroll
            for (int t = 0; t < NT; ++t) {
                uint2 bl = *(const uint2*)(B + (uint32_t)(ntb + t) * 64u + boff);
                #pragma unroll
                for (int mb = 0; mb < 2; ++mb)
                    mma_k16(acc[mb][t], ah[mb][0], ah[mb][1], ah[mb][2], ah[mb][3], bl.x, bl.y);
            }
        }
    }
    __syncthreads();   // all compute done: wbuf ring dead, red/outAcc overlays safe

    // ---- epilogue: per-thread row slots mb*16 + r (+8) ----
    float sv[2][2], qv[2][2];
    #pragma unroll
    for (int mb = 0; mb < 2; ++mb) { sv[mb][0] = sv[mb][1] = qv[mb][0] = qv[mb][1] = 0.f; }
    #pragma unroll
    for (int t = 0; t < NT; ++t) {
        float2 bv = *(const float2*)(bias + 8 * (ntb + t) + 2 * cp);   // gmem, L2-hot
        #pragma unroll
        for (int mb = 0; mb < 2; ++mb) {
            acc[mb][t][0] += bv.x; acc[mb][t][1] += bv.y;
            acc[mb][t][2] += bv.x; acc[mb][t][3] += bv.y;
            sv[mb][0] += acc[mb][t][0] + acc[mb][t][1];
            qv[mb][0] += acc[mb][t][0] * acc[mb][t][0] + acc[mb][t][1] * acc[mb][t][1];
            sv[mb][1] += acc[mb][t][2] + acc[mb][t][3];
            qv[mb][1] += acc[mb][t][2] * acc[mb][t][2] + acc[mb][t][3] * acc[mb][t][3];
        }
    }
    #pragma unroll
    for (int o = 1; o <= 2; o <<= 1)
        #pragma unroll
        for (int mb = 0; mb < 2; ++mb)
            #pragma unroll
            for (int h = 0; h < 2; ++h) {
                sv[mb][h] += __shfl_xor_sync(0xffffffffu, sv[mb][h], o);
                qv[mb][h] += __shfl_xor_sync(0xffffffffu, qv[mb][h], o);
            }
    if (cp == 0) {
        #pragma unroll
        for (int mb = 0; mb < 2; ++mb)
            #pragma unroll
            for (int h = 0; h < 2; ++h) {
                int row = mb * 16 + r + 8 * h;
                red[(w * 32 + row) * 2 + 0] = sv[mb][h];
                red[(w * 32 + row) * 2 + 1] = qv[mb][h];
            }
    }
    __syncthreads();

    float mean_[2][2], rstd_[2][2];
    #pragma unroll
    for (int mb = 0; mb < 2; ++mb)
        #pragma unroll
        for (int h = 0; h < 2; ++h) {
            int row = mb * 16 + r + 8 * h;
            float S = 0.f, Q = 0.f;
            #pragma unroll
            for (int g = 0; g < 8; ++g) {
                float2 e = *(const float2*)(red + (g * 32 + row) * 2);
                S += e.x; Q += e.y;
            }
            float m = S * (1.0f / HOUT);
            mean_[mb][h] = m;
            rstd_[mb][h] = rsqrtf(Q * (1.0f / HOUT) - m * m + 1e-5f);
        }

    if (!LAST) {
        #pragma unroll
        for (int t = 0; t < NT; ++t) {
            int col0 = 8 * (ntb + t) + 2 * cp;
            float2 lwv = *(const float2*)(lnw + col0);
            float2 lbv = *(const float2*)(lnb + col0);
            #pragma unroll
            for (int mb = 0; mb < 2; ++mb) {
                float y00 = fmaxf((acc[mb][t][0] - mean_[mb][0]) * rstd_[mb][0] * lwv.x + lbv.x, 0.f);
                float y01 = fmaxf((acc[mb][t][1] - mean_[mb][0]) * rstd_[mb][0] * lwv.y + lbv.y, 0.f);
                float y10 = fmaxf((acc[mb][t][2] - mean_[mb][1]) * rstd_[mb][1] * lwv.x + lbv.x, 0.f);
                float y11 = fmaxf((acc[mb][t][3] - mean_[mb][1]) * rstd_[mb][1] * lwv.y + lbv.y, 0.f);
                uint32_t lo0, lo1;
                uint32_t hi0 = pack_split(y00, y01, lo0);
                uint32_t hi1 = pack_split(y10, y11, lo1);
                uint32_t idx0 = (uint32_t)((ntb + t) * TMR + mb * 16 + r) * 4u + cp;
                actHi[idx0] = hi0;      actLo[idx0] = lo0;
                actHi[idx0 + 32] = hi1; actLo[idx0 + 32] = lo1;
            }
        }
        __syncthreads();
    } else {
        float p[2][2][3];
        #pragma unroll
        for (int mb = 0; mb < 2; ++mb)
            #pragma unroll
            for (int h = 0; h < 2; ++h)
                p[mb][h][0] = p[mb][h][1] = p[mb][h][2] = 0.f;
        #pragma unroll
        for (int t = 0; t < NT; ++t) {
            int col0 = 8 * (ntb + t) + 2 * cp;
            float2 lwv = *(const float2*)(lnw + col0);
            float2 lbv = *(const float2*)(lnb + col0);
            float2 wo[3];
            #pragma unroll
            for (int o = 0; o < 3; ++o) wo[o] = *(const float2*)(W_out + o * 512 + col0);
            #pragma unroll
            for (int mb = 0; mb < 2; ++mb) {
                float y00 = fmaxf((acc[mb][t][0] - mean_[mb][0]) * rstd_[mb][0] * lwv.x + lbv.x, 0.f);
                float y01 = fmaxf((acc[mb][t][1] - mean_[mb][0]) * rstd_[mb][0] * lwv.y + lbv.y, 0.f);
                float y10 = fmaxf((acc[mb][t][2] - mean_[mb][1]) * rstd_[mb][1] * lwv.x + lbv.x, 0.f);
                float y11 = fmaxf((acc[mb][t][3] - mean_[mb][1]) * rstd_[mb][1] * lwv.y + lbv.y, 0.f);
                #pragma unroll
                for (int o = 0; o < 3; ++o) {
                    p[mb][0][o] += y00 * wo[o].x + y01 * wo[o].y;
                    p[mb][1][o] += y10 * wo[o].x + y11 * wo[o].y;
                }
            }
        }
        #pragma unroll
        for (int o = 0; o < 3; ++o)
            #pragma unroll
            for (int mb = 0; mb < 2; ++mb)
                #pragma unroll
                for (int h = 0; h < 2; ++h) {
                    p[mb][h][o] += __shfl_xor_sync(0xffffffffu, p[mb][h][o], 1);
                    p[mb][h][o] += __shfl_xor_sync(0xffffffffu, p[mb][h][o], 2);
                }
        if (cp == 0) {
            #pragma unroll
            for (int mb = 0; mb < 2; ++mb)
                #pragma unroll
                for (int h = 0; h < 2; ++h) {
                    int row = mb * 16 + r + 8 * h;
                    #pragma unroll
                    for (int o = 0; o < 3; ++o)
                        outAcc[(w * 32 + row) * 3 + o] = p[mb][h][o];
                }
        }
        __syncthreads();
        if (tid < 96) {
            int row = tid / 3, o = tid - row * 3;
            float v = b_out[o];
            #pragma unroll
            for (int g = 0; g < 8; ++g) v += outAcc[(g * 32 + row) * 3 + o];
            out[(size_t)(rowbase + row) * 9 + fidx * 3 + o] = v;
        }
    }
}

// ---------------- fused kernel per factor ----------------
template<int F>
__global__ void __launch_bounds__(NTHR, 2) mipnet_tc(
    const float* __restrict__ inputs,
    const float* __restrict__ W_in, const float* __restrict__ b_in,
    const float* __restrict__ bs,
    const float* __restrict__ ln_w, const float* __restrict__ ln_b,
    const float* __restrict__ W_out, const float* __restrict__ b_out,
    float* __restrict__ out)
{
    extern __shared__ uint8_t sm[];
    const int tid  = threadIdx.x;
    const int lane = tid & 31;
    const int w    = tid >> 5;    // warp = column eighth, all 32 rows
    const int rowbase = blockIdx.x * TMR;

    layer0<hdim<F>(0)>(sm, inputs, W_in, b_in, ln_w, ln_b, rowbase);
    mid_layer<hdim<F>(0), hdim<F>(1), false>(sm, lane, w, 0, F, bs,
        ln_w + 512,  ln_b + 512,  W_out, b_out, out, rowbase);
    mid_layer<hdim<F>(1), hdim<F>(2), false>(sm, lane, w, 1, F, bs + 512,
        ln_w + 1024, ln_b + 1024, W_out, b_out, out, rowbase);
    mid_layer<hdim<F>(2), hdim<F>(3), false>(sm, lane, w, 2, F, bs + 1024,
        ln_w + 1536, ln_b + 1536, W_out, b_out, out, rowbase);
    mid_layer<hdim<F>(3), hdim<F>(4), false>(sm, lane, w, 3, F, bs + 1536,
        ln_w + 2048, ln_b + 2048, W_out, b_out, out, rowbase);
    mid_layer<hdim<F>(4), hdim<F>(5), false>(sm, lane, w, 4, F, bs + 2048,
        ln_w + 2560, ln_b + 2560, W_out, b_out, out, rowbase);
    mid_layer<hdim<F>(5), hdim<F>(6), true >(sm, lane, w, 5, F, bs + 2560,
        ln_w + 3072, ln_b + 3072, W_out, b_out, out, rowbase);
}

extern "C" void kernel_launch(void* const* d_in, const int* in_sizes, int n_in,
                              void* d_out, int out_size) {
    const float* inputs = (const float*)d_in[0];
    const float* W_in   = (const float*)d_in[1];
    const float* b_in   = (const float*)d_in[2];
    const float* Ws     = (const float*)d_in[3];
    const float* bs     = (const float*)d_in[4];
    const float* ln_w   = (const float*)d_in[5];
    const float* ln_b   = (const float*)d_in[6];
    const float* W_out  = (const float*)d_in[7];
    const float* b_out  = (const float*)d_in[8];
    float* out = (float*)d_out;

    const int Nrows = in_sizes[0] / 6;
    const int tiles = Nrows / TMR;      // 4096

    cudaFuncSetAttribute(mipnet_tc<0>, cudaFuncAttributeMaxDynamicSharedMemorySize, SM_TOTAL);
    cudaFuncSetAttribute(mipnet_tc<1>, cudaFuncAttributeMaxDynamicSharedMemorySize, SM_TOTAL);
    cudaFuncSetAttribute(mipnet_tc<2>, cudaFuncAttributeMaxDynamicSharedMemorySize, SM_TOTAL);

    split_weights<<<3072, 256>>>(Ws);

    mipnet_tc<0><<<tiles, NTHR, SM_TOTAL>>>(inputs, W_in, b_in, bs, ln_w, ln_b, W_out, b_out, out);
    mipnet_tc<1><<<tiles, NTHR, SM_TOTAL>>>(inputs, W_in, b_in, bs, ln_w, ln_b, W_out, b_out, out);
    mipnet_tc<2><<<tiles, NTHR, SM_TOTAL>>>(inputs, W_in, b_in, bs, ln_w, ln_b, W_out, b_out, out);
}

// round 15
// speedup vs baseline: 1.2377x; 1.2377x over previous
#include <cuda_runtime.h>
#include <cuda_bf16.h>
#include <cstdint>

#define NTHR 256
#define TMR  32

// Weight blob (k16 layout): per layer 32 k16-chunks x [hl][n][pos].
// word(l, kt, hl, n, pos) at (l*32+kt)*8192 + hl*4096 + n*8 + pos,
// pos = 2*(kpl&3) + (kpl>>2) for k-pair kpl (0..7): B-fragment pair (kpl, kpl+4)
// is one contiguous 8B load: uint2 at  nt*64 + (lane>>2)*8 + 2*(lane&3).
// Plane units are contiguous: unit u = (kt*2+hl) lives at  u*4096 words.
__device__ __align__(16) uint32_t gW[6u * 262144u];   // 6 MB

// ---- smem byte offsets ----
#define SM_ACT_HI 0         // 8192 words (32 rows x 512 cols bf16-pairs)
#define SM_ACT_LO 32768     // 8192 words
#define SM_WBUF   65536     // 48 KB: per-warp 3-buffer ring (8 warps x 3 x 512 words)
#define SM_TOTAL  114688    // 112 KB -> 2 CTAs/SM
// overlays inside WBUF (used only when ALL warps' rings are dead, barrier-protected):
#define SM_XIN    SM_WBUF             // layer0 input staging (768 B)
#define SM_L0W    (SM_WBUF + 1024)    // layer0 W_in (<=12 KB)
#define SM_L0B    (SM_WBUF + 16384)   // layer0 bias (2 KB)
#define SM_L0LW   (SM_WBUF + 18432)   // layer0 ln_w (2 KB)
#define SM_L0LB   (SM_WBUF + 20480)   // layer0 ln_b (2 KB)
#define SM_RED    SM_WBUF             // epilogue row stats (2 KB)
#define SM_OUTACC (SM_WBUF + 2048)    // LAST epilogue partials (3 KB)

__device__ __forceinline__ void cp16(void* dst, const void* src) {
    unsigned s = (unsigned)__cvta_generic_to_shared(dst);
    asm volatile("cp.async.cg.shared.global [%0], [%1], 16;" :: "r"(s), "l"(src));
}
__device__ __forceinline__ void cp_commit() { asm volatile("cp.async.commit_group;"); }
__device__ __forceinline__ void cp_wait0()  { asm volatile("cp.async.wait_group 0;"); }
__device__ __forceinline__ void cp_wait1()  { asm volatile("cp.async.wait_group 1;"); }

__device__ __forceinline__ void mma_k16(float* d,
                                        uint32_t a0, uint32_t a1, uint32_t a2, uint32_t a3,
                                        uint32_t b0, uint32_t b1) {
    asm volatile("mma.sync.aligned.m16n8k16.row.col.f32.bf16.bf16.f32 "
        "{%0,%1,%2,%3}, {%4,%5,%6,%7}, {%8,%9}, {%0,%1,%2,%3};"
        : "+f"(d[0]), "+f"(d[1]), "+f"(d[2]), "+f"(d[3])
        : "r"(a0), "r"(a1), "r"(a2), "r"(a3), "r"(b0), "r"(b1));
}

__device__ __forceinline__ uint32_t pack_split(float a, float b, uint32_t& lo) {
    __nv_bfloat16 ha = __float2bfloat16(a), hb = __float2bfloat16(b);
    __nv_bfloat16 la = __float2bfloat16(a - __bfloat162float(ha));
    __nv_bfloat16 lb = __float2bfloat16(b - __bfloat162float(hb));
    lo = (uint32_t)__bfloat16_as_ushort(la) | ((uint32_t)__bfloat16_as_ushort(lb) << 16);
    return (uint32_t)__bfloat16_as_ushort(ha) | ((uint32_t)__bfloat16_as_ushort(hb) << 16);
}

template<int F>
__host__ __device__ constexpr int hdim(int l) {
    return (F == 0) ? 256 : ((F == 2) ? 512 : ((l % 2 == 0) ? 512 : 256));
}

// ---------------- prep: split fp32 weights into hi/lo bf16 blob (k16 layout) ----
__global__ void split_weights(const float* __restrict__ Ws) {
    int id = blockIdx.x * 256 + threadIdx.x;        // 6*512*256 k-pairs
    int l  = id / (512 * 256);
    int r  = id - l * (512 * 256);
    int n  = r >> 8;
    int kp = r & 255;
    const float* W = Ws + ((size_t)l * 512 + n) * 512;
    float w0 = W[2 * kp], w1 = W[2 * kp + 1];
    __nv_bfloat16 h0 = __float2bfloat16(w0), h1 = __float2bfloat16(w1);
    __nv_bfloat16 l0 = __float2bfloat16(w0 - __bfloat162float(h0));
    __nv_bfloat16 l1 = __float2bfloat16(w1 - __bfloat162float(h1));
    int kt = kp >> 3, kpl = kp & 7;
    int pos = 2 * (kpl & 3) + (kpl >> 2);
    uint32_t base = (uint32_t)((l * 32 + kt) * 2) * 4096u + (uint32_t)(n * 8 + pos);
    gW[base]        = (uint32_t)__bfloat16_as_ushort(h0) | ((uint32_t)__bfloat16_as_ushort(h1) << 16);
    gW[base + 4096] = (uint32_t)__bfloat16_as_ushort(l0) | ((uint32_t)__bfloat16_as_ushort(l1) << 16);
}

// ---------------- layer 0 (K = 6) ----------------
template<int HOUT>
__device__ __noinline__ void layer0(uint8_t* sm,
    const float* __restrict__ inputs, const float* __restrict__ W_in,
    const float* __restrict__ b_in, const float* __restrict__ lnw,
    const float* __restrict__ lnb, int rowbase)
{
    uint32_t* actHi = (uint32_t*)(sm + SM_ACT_HI);
    uint32_t* actLo = (uint32_t*)(sm + SM_ACT_LO);
    float* xin   = (float*)(sm + SM_XIN);
    float* sW    = (float*)(sm + SM_L0W);
    float* sBias = (float*)(sm + SM_L0B);
    float* sLw   = (float*)(sm + SM_L0LW);
    float* sLb   = (float*)(sm + SM_L0LB);
    const int tid = threadIdx.x;

    for (int i = tid; i < HOUT * 6; i += NTHR) sW[i] = W_in[i];
    for (int i = tid; i < HOUT; i += NTHR) { sBias[i] = b_in[i]; sLw[i] = lnw[i]; sLb[i] = lnb[i]; }
    for (int i = tid; i < TMR * 6; i += NTHR) xin[i] = inputs[rowbase * 6 + i];
    __syncthreads();

    const int row = tid >> 3, sub = (tid >> 2) & 1, cp = tid & 3;
    float x[6];
    #pragma unroll
    for (int k = 0; k < 6; ++k) x[k] = xin[row * 6 + k];

    float s = 0.f, q = 0.f;
    for (int nt = sub; nt < HOUT / 8; nt += 2) {
        #pragma unroll
        for (int e = 0; e < 2; ++e) {
            int col = 8 * nt + 2 * cp + e;
            const float* w = sW + col * 6;
            float v = sBias[col];
            #pragma unroll
            for (int k = 0; k < 6; ++k) v += x[k] * w[k];
            s += v; q += v * v;
        }
    }
    #pragma unroll
    for (int o = 1; o <= 4; o <<= 1) {
        s += __shfl_xor_sync(0xffffffffu, s, o);
        q += __shfl_xor_sync(0xffffffffu, q, o);
    }
    const float mean = s * (1.0f / HOUT);
    const float rstd = rsqrtf(q * (1.0f / HOUT) - mean * mean + 1e-5f);

    for (int nt = sub; nt < HOUT / 8; nt += 2) {
        float y[2];
        #pragma unroll
        for (int e = 0; e < 2; ++e) {
            int col = 8 * nt + 2 * cp + e;
            const float* w = sW + col * 6;
            float v = sBias[col];
            #pragma unroll
            for (int k = 0; k < 6; ++k) v += x[k] * w[k];
            y[e] = fmaxf((v - mean) * rstd * sLw[col] + sLb[col], 0.f);
        }
        uint32_t lo;
        uint32_t hi = pack_split(y[0], y[1], lo);
        uint32_t idx = (uint32_t)(nt * TMR + row) * 4u + (uint32_t)cp;
        actHi[idx] = hi; actLo[idx] = lo;
    }
    __syncthreads();
}

// ---- mid layer: k16 HMMA 3-split GEMM, warp-private plane ring (NO mainloop barriers) ----
template<int HIN, int HOUT, bool LAST>
__device__ __noinline__ void mid_layer(uint8_t* sm, int lane, int w,
    int lidx, int fidx,
    const float* __restrict__ bias, const float* __restrict__ lnw,
    const float* __restrict__ lnb, const float* __restrict__ W_out,
    const float* __restrict__ b_out, float* __restrict__ out, int rowbase)
{
    constexpr int KT  = HIN / 16;          // k16 chunks
    constexpr int NU  = 2 * KT;            // plane units
    constexpr int NT  = HOUT / 64;         // n8-tiles per warp
    constexpr int SW  = NT * 64;           // slice words per plane per warp
    constexpr int NJ  = NT / 2;            // cp16 per lane per plane slice

    uint32_t* actHi = (uint32_t*)(sm + SM_ACT_HI);
    uint32_t* actLo = (uint32_t*)(sm + SM_ACT_LO);
    uint32_t* wbuf  = (uint32_t*)(sm + SM_WBUF);
    float* red    = (float*)(sm + SM_RED);
    float* outAcc = (float*)(sm + SM_OUTACC);
    const int tid = threadIdx.x;

    const int r  = lane >> 2;
    const int cp = lane & 3;
    const int ntb = w * NT;
    const uint32_t boff = (uint32_t)(r * 8 + 2 * cp);

    // warp-private 3-buffer ring, 512 words per buffer
    uint32_t* wb = wbuf + w * 1536;
    // warp slice of plane unit u lives at  gW + lidx*262144 + u*4096 + ntb*64
    const uint32_t* wsl = gW + (uint32_t)lidx * 262144u + (uint32_t)ntb * 64u + (uint32_t)(lane * 4);

    auto stageu = [&](int u, int b) {
        const uint32_t* src = wsl + (uint32_t)u * 4096u;
        uint32_t* dst = wb + b * 512 + lane * 4;
        #pragma unroll
        for (int j = 0; j < NJ; ++j)
            cp16(dst + j * 128, src + j * 128);
        cp_commit();
    };

    float acc[2][NT][4];
    #pragma unroll
    for (int mb = 0; mb < 2; ++mb)
        #pragma unroll
        for (int t = 0; t < NT; ++t)
            acc[mb][t][0] = acc[mb][t][1] = acc[mb][t][2] = acc[mb][t][3] = 0.f;

    uint32_t ah[2][4];   // hi A-frags persist from hi-unit to lo-unit

    stageu(0, 0);
    if (NU > 1) stageu(1, 1);

    int b = 0;
    #pragma unroll 2
    for (int u = 0; u < NU; ++u) {
        if (u + 1 < NU) cp_wait1(); else cp_wait0();
        __syncwarp();
        if (u + 2 < NU) {
            int b2 = b + 2; if (b2 >= 3) b2 -= 3;
            stageu(u + 2, b2);
        }

        const uint32_t* B = wb + b * 512;
        const int kt = u >> 1;

        if ((u & 1) == 0) {
            uint32_t al[2][4];
            #pragma unroll
            for (int mb = 0; mb < 2; ++mb) {
                uint32_t i0 = (uint32_t)((2 * kt) * TMR + mb * 16 + r) * 4u + cp;
                uint32_t i2 = i0 + (uint32_t)(TMR * 4);
                ah[mb][0] = actHi[i0]; ah[mb][1] = actHi[i0 + 32];
                ah[mb][2] = actHi[i2]; ah[mb][3] = actHi[i2 + 32];
                al[mb][0] = actLo[i0]; al[mb][1] = actLo[i0 + 32];
                al[mb][2] = actLo[i2]; al[mb][3] = actLo[i2 + 32];
            }
            #pragma unroll
            for (int t = 0; t < NT; ++t) {
                uint2 bh = *(const uint2*)(B + (uint32_t)t * 64u + boff);
                #pragma unroll
                for (int mb = 0; mb < 2; ++mb) {
                    mma_k16(acc[mb][t], ah[mb][0], ah[mb][1], ah[mb][2], ah[mb][3], bh.x, bh.y);
                    mma_k16(acc[mb][t], al[mb][0], al[mb][1], al[mb][2], al[mb][3], bh.x, bh.y);
                }
            }
        } else {
            #pragma unroll
            for (int t = 0; t < NT; ++t) {
                uint2 bl = *(const uint2*)(B + (uint32_t)t * 64u + boff);
                #pragma unroll
                for (int mb = 0; mb < 2; ++mb)
                    mma_k16(acc[mb][t], ah[mb][0], ah[mb][1], ah[mb][2], ah[mb][3], bl.x, bl.y);
            }
        }
        b = (b == 2) ? 0 : b + 1;
    }

    // ---- epilogue: per-thread row slots mb*16 + r (+8) ----
    float sv[2][2], qv[2][2];
    #pragma unroll
    for (int mb = 0; mb < 2; ++mb) { sv[mb][0] = sv[mb][1] = qv[mb][0] = qv[mb][1] = 0.f; }
    #pragma unroll
    for (int t = 0; t < NT; ++t) {
        float2 bv = *(const float2*)(bias + 8 * (ntb + t) + 2 * cp);   // gmem, L2-hot
        #pragma unroll
        for (int mb = 0; mb < 2; ++mb) {
            acc[mb][t][0] += bv.x; acc[mb][t][1] += bv.y;
            acc[mb][t][2] += bv.x; acc[mb][t][3] += bv.y;
            sv[mb][0] += acc[mb][t][0] + acc[mb][t][1];
            qv[mb][0] += acc[mb][t][0] * acc[mb][t][0] + acc[mb][t][1] * acc[mb][t][1];
            sv[mb][1] += acc[mb][t][2] + acc[mb][t][3];
            qv[mb][1] += acc[mb][t][2] * acc[mb][t][2] + acc[mb][t][3] * acc[mb][t][3];
        }
    }
    #pragma unroll
    for (int o = 1; o <= 2; o <<= 1)
        #pragma unroll
        for (int mb = 0; mb < 2; ++mb)
            #pragma unroll
            for (int h = 0; h < 2; ++h) {
                sv[mb][h] += __shfl_xor_sync(0xffffffffu, sv[mb][h], o);
                qv[mb][h] += __shfl_xor_sync(0xffffffffu, qv[mb][h], o);
            }

    __syncthreads();   // ALL warps done: mainloop reads of act finished, rings dead -> overlays safe

    if (cp == 0) {
        #pragma unroll
        for (int mb = 0; mb < 2; ++mb)
            #pragma unroll
            for (int h = 0; h < 2; ++h) {
                int row = mb * 16 + r + 8 * h;
                red[(w * 32 + row) * 2 + 0] = sv[mb][h];
                red[(w * 32 + row) * 2 + 1] = qv[mb][h];
            }
    }
    __syncthreads();

    float mean_[2][2], rstd_[2][2];
    #pragma unroll
    for (int mb = 0; mb < 2; ++mb)
        #pragma unroll
        for (int h = 0; h < 2; ++h) {
            int row = mb * 16 + r + 8 * h;
            float S = 0.f, Q = 0.f;
            #pragma unroll
            for (int g = 0; g < 8; ++g) {
                float2 e = *(const float2*)(red + (g * 32 + row) * 2);
                S += e.x; Q += e.y;
            }
            float m = S * (1.0f / HOUT);
            mean_[mb][h] = m;
            rstd_[mb][h] = rsqrtf(Q * (1.0f / HOUT) - m * m + 1e-5f);
        }

    if (!LAST) {
        #pragma unroll
        for (int t = 0; t < NT; ++t) {
            int col0 = 8 * (ntb + t) + 2 * cp;
            float2 lwv = *(const float2*)(lnw + col0);
            float2 lbv = *(const float2*)(lnb + col0);
            #pragma unroll
            for (int mb = 0; mb < 2; ++mb) {
                float y00 = fmaxf((acc[mb][t][0] - mean_[mb][0]) * rstd_[mb][0] * lwv.x + lbv.x, 0.f);
                float y01 = fmaxf((acc[mb][t][1] - mean_[mb][0]) * rstd_[mb][0] * lwv.y + lbv.y, 0.f);
                float y10 = fmaxf((acc[mb][t][2] - mean_[mb][1]) * rstd_[mb][1] * lwv.x + lbv.x, 0.f);
                float y11 = fmaxf((acc[mb][t][3] - mean_[mb][1]) * rstd_[mb][1] * lwv.y + lbv.y, 0.f);
                uint32_t lo0, lo1;
                uint32_t hi0 = pack_split(y00, y01, lo0);
                uint32_t hi1 = pack_split(y10, y11, lo1);
                uint32_t idx0 = (uint32_t)((ntb + t) * TMR + mb * 16 + r) * 4u + cp;
                actHi[idx0] = hi0;      actLo[idx0] = lo0;
                actHi[idx0 + 32] = hi1; actLo[idx0 + 32] = lo1;
            }
        }
        __syncthreads();
    } else {
        float p[2][2][3];
        #pragma unroll
        for (int mb = 0; mb < 2; ++mb)
            #pragma unroll
            for (int h = 0; h < 2; ++h)
                p[mb][h][0] = p[mb][h][1] = p[mb][h][2] = 0.f;
        #pragma unroll
        for (int t = 0; t < NT; ++t) {
            int col0 = 8 * (ntb + t) + 2 * cp;
            float2 lwv = *(const float2*)(lnw + col0);
            float2 lbv = *(const float2*)(lnb + col0);
            float2 wo[3];
            #pragma unroll
            for (int o = 0; o < 3; ++o) wo[o] = *(const float2*)(W_out + o * 512 + col0);
            #pragma unroll
            for (int mb = 0; mb < 2; ++mb) {
                float y00 = fmaxf((acc[mb][t][0] - mean_[mb][0]) * rstd_[mb][0] * lwv.x + lbv.x, 0.f);
                float y01 = fmaxf((acc[mb][t][1] - mean_[mb][0]) * rstd_[mb][0] * lwv.y + lbv.y, 0.f);
                float y10 = fmaxf((acc[mb][t][2] - mean_[mb][1]) * rstd_[mb][1] * lwv.x + lbv.x, 0.f);
                float y11 = fmaxf((acc[mb][t][3] - mean_[mb][1]) * rstd_[mb][1] * lwv.y + lbv.y, 0.f);
                #pragma unroll
                for (int o = 0; o < 3; ++o) {
                    p[mb][0][o] += y00 * wo[o].x + y01 * wo[o].y;
                    p[mb][1][o] += y10 * wo[o].x + y11 * wo[o].y;
                }
            }
        }
        #pragma unroll
        for (int o = 0; o < 3; ++o)
            #pragma unroll
            for (int mb = 0; mb < 2; ++mb)
                #pragma unroll
                for (int h = 0; h < 2; ++h) {
                    p[mb][h][o] += __shfl_xor_sync(0xffffffffu, p[mb][h][o], 1);
                    p[mb][h][o] += __shfl_xor_sync(0xffffffffu, p[mb][h][o], 2);
                }
        if (cp == 0) {
            #pragma unroll
            for (int mb = 0; mb < 2; ++mb)
                #pragma unroll
                for (int h = 0; h < 2; ++h) {
                    int row = mb * 16 + r + 8 * h;
                    #pragma unroll
                    for (int o = 0; o < 3; ++o)
                        outAcc[(w * 32 + row) * 3 + o] = p[mb][h][o];
                }
        }
        __syncthreads();
        if (tid < 96) {
            int row = tid / 3, o = tid - row * 3;
            float v = b_out[o];
            #pragma unroll
            for (int g = 0; g < 8; ++g) v += outAcc[(g * 32 + row) * 3 + o];
            out[(size_t)(rowbase + row) * 9 + fidx * 3 + o] = v;
        }
    }
}

// ---------------- fused kernel per factor ----------------
template<int F>
__global__ void __launch_bounds__(NTHR, 2) mipnet_tc(
    const float* __restrict__ inputs,
    const float* __restrict__ W_in, const float* __restrict__ b_in,
    const float* __restrict__ bs,
    const float* __restrict__ ln_w, const float* __restrict__ ln_b,
    const float* __restrict__ W_out, const float* __restrict__ b_out,
    float* __restrict__ out)
{
    extern __shared__ uint8_t sm[];
    const int tid  = threadIdx.x;
    const int lane = tid & 31;
    const int w    = tid >> 5;    // warp = column eighth, all 32 rows
    const int rowbase = blockIdx.x * TMR;

    layer0<hdim<F>(0)>(sm, inputs, W_in, b_in, ln_w, ln_b, rowbase);
    mid_layer<hdim<F>(0), hdim<F>(1), false>(sm, lane, w, 0, F, bs,
        ln_w + 512,  ln_b + 512,  W_out, b_out, out, rowbase);
    mid_layer<hdim<F>(1), hdim<F>(2), false>(sm, lane, w, 1, F, bs + 512,
        ln_w + 1024, ln_b + 1024, W_out, b_out, out, rowbase);
    mid_layer<hdim<F>(2), hdim<F>(3), false>(sm, lane, w, 2, F, bs + 1024,
        ln_w + 1536, ln_b + 1536, W_out, b_out, out, rowbase);
    mid_layer<hdim<F>(3), hdim<F>(4), false>(sm, lane, w, 3, F, bs + 1536,
        ln_w + 2048, ln_b + 2048, W_out, b_out, out, rowbase);
    mid_layer<hdim<F>(4), hdim<F>(5), false>(sm, lane, w, 4, F, bs + 2048,
        ln_w + 2560, ln_b + 2560, W_out, b_out, out, rowbase);
    mid_layer<hdim<F>(5), hdim<F>(6), true >(sm, lane, w, 5, F, bs + 2560,
        ln_w + 3072, ln_b + 3072, W_out, b_out, out, rowbase);
}

extern "C" void kernel_launch(void* const* d_in, const int* in_sizes, int n_in,
                              void* d_out, int out_size) {
    const float* inputs = (const float*)d_in[0];
    const float* W_in   = (const float*)d_in[1];
    const float* b_in   = (const float*)d_in[2];
    const float* Ws     = (const float*)d_in[3];
    const float* bs     = (const float*)d_in[4];
    const float* ln_w   = (const float*)d_in[5];
    const float* ln_b   = (const float*)d_in[6];
    const float* W_out  = (const float*)d_in[7];
    const float* b_out  = (const float*)d_in[8];
    float* out = (float*)d_out;

    const int Nrows = in_sizes[0] / 6;
    const int tiles = Nrows / TMR;      // 4096

    cudaFuncSetAttribute(mipnet_tc<0>, cudaFuncAttributeMaxDynamicSharedMemorySize, SM_TOTAL);
    cudaFuncSetAttribute(mipnet_tc<1>, cudaFuncAttributeMaxDynamicSharedMemorySize, SM_TOTAL);
    cudaFuncSetAttribute(mipnet_tc<2>, cudaFuncAttributeMaxDynamicSharedMemorySize, SM_TOTAL);

    split_weights<<<3072, 256>>>(Ws);

    mipnet_tc<0><<<tiles, NTHR, SM_TOTAL>>>(inputs, W_in, b_in, bs, ln_w, ln_b, W_out, b_out, out);
    mipnet_tc<1><<<tiles, NTHR, SM_TOTAL>>>(inputs, W_in, b_in, bs, ln_w, ln_b, W_out, b_out, out);
    mipnet_tc<2><<<tiles, NTHR, SM_TOTAL>>>(inputs, W_in, b_in, bs, ln_w, ln_b, W_out, b_out, out);
}

// round 16
// speedup vs baseline: 1.2615x; 1.0193x over previous
#include <cuda_runtime.h>
#include <cuda_bf16.h>
#include <cstdint>

#define NTHR 256
#define TMR  32

// Weight blob (k16 layout): per layer 32 k16-chunks x [hl][n][pos].
// word(l, kt, hl, n, pos) at (l*32+kt)*8192 + hl*4096 + n*8 + pos,
// pos = 2*(kpl&3) + (kpl>>2) for k-pair kpl (0..7): B-fragment pair (kpl, kpl+4)
// is one contiguous 8B load: uint2 at  nt*64 + (lane>>2)*8 + 2*(lane&3).
// Plane units are contiguous: unit u = (kt*2+hl) lives at  u*4096 words.
__device__ __align__(16) uint32_t gW[6u * 262144u];   // 6 MB

// ---- smem byte offsets ----
#define SM_ACT_HI 0         // 8192 words (32 rows x 512 cols bf16-pairs)
#define SM_ACT_LO 32768     // 8192 words
#define SM_WBUF   65536     // 48 KB: per-warp 3-buffer ring (8 warps x 3 x 512 words)
#define SM_TOTAL  114688    // 112 KB -> 2 CTAs/SM
// overlays inside WBUF:
#define SM_XIN    SM_WBUF             // layer0 input staging (768 B)            [layer0 only]
#define SM_L0W    (SM_WBUF + 1024)    // layer0 W_in (<=12 KB)                   [layer0 only]
#define SM_L0B    (SM_WBUF + 16384)   // layer0 bias (2 KB)                      [layer0 only]
#define SM_L0LW   (SM_WBUF + 18432)   // layer0 ln_w (2 KB)                      [layer0 only]
#define SM_L0LB   (SM_WBUF + 20480)   // layer0 ln_b (2 KB)                      [layer0 only]
#define SM_OUTACC (SM_WBUF + 2048)    // LAST epilogue partials (3 KB)           [LAST only, no prefetch]
// red lives in warp 7's ring buffer 2 (last 2 KB of ring): early prefetch only
// touches buffers 0/1, and buffer 2 of the next layer is staged only after the
// epilogue's final barrier, when red is dead.
#define SM_RED    (SM_WBUF + 47104)   // epilogue row stats (2 KB)

__device__ __forceinline__ void cp16(void* dst, const void* src) {
    unsigned s = (unsigned)__cvta_generic_to_shared(dst);
    asm volatile("cp.async.cg.shared.global [%0], [%1], 16;" :: "r"(s), "l"(src));
}
__device__ __forceinline__ void cp_commit() { asm volatile("cp.async.commit_group;"); }
__device__ __forceinline__ void cp_wait0()  { asm volatile("cp.async.wait_group 0;"); }
__device__ __forceinline__ void cp_wait1()  { asm volatile("cp.async.wait_group 1;"); }

__device__ __forceinline__ void mma_k16(float* d,
                                        uint32_t a0, uint32_t a1, uint32_t a2, uint32_t a3,
                                        uint32_t b0, uint32_t b1) {
    asm volatile("mma.sync.aligned.m16n8k16.row.col.f32.bf16.bf16.f32 "
        "{%0,%1,%2,%3}, {%4,%5,%6,%7}, {%8,%9}, {%0,%1,%2,%3};"
        : "+f"(d[0]), "+f"(d[1]), "+f"(d[2]), "+f"(d[3])
        : "r"(a0), "r"(a1), "r"(a2), "r"(a3), "r"(b0), "r"(b1));
}

__device__ __forceinline__ uint32_t pack_split(float a, float b, uint32_t& lo) {
    __nv_bfloat16 ha = __float2bfloat16(a), hb = __float2bfloat16(b);
    __nv_bfloat16 la = __float2bfloat16(a - __bfloat162float(ha));
    __nv_bfloat16 lb = __float2bfloat16(b - __bfloat162float(hb));
    lo = (uint32_t)__bfloat16_as_ushort(la) | ((uint32_t)__bfloat16_as_ushort(lb) << 16);
    return (uint32_t)__bfloat16_as_ushort(ha) | ((uint32_t)__bfloat16_as_ushort(hb) << 16);
}

template<int F>
__host__ __device__ constexpr int hdim(int l) {
    return (F == 0) ? 256 : ((F == 2) ? 512 : ((l % 2 == 0) ? 512 : 256));
}

// ---------------- prep: split fp32 weights into hi/lo bf16 blob (k16 layout) ----
__global__ void split_weights(const float* __restrict__ Ws) {
    int id = blockIdx.x * 256 + threadIdx.x;        // 6*512*256 k-pairs
    int l  = id / (512 * 256);
    int r  = id - l * (512 * 256);
    int n  = r >> 8;
    int kp = r & 255;
    const float* W = Ws + ((size_t)l * 512 + n) * 512;
    float w0 = W[2 * kp], w1 = W[2 * kp + 1];
    __nv_bfloat16 h0 = __float2bfloat16(w0), h1 = __float2bfloat16(w1);
    __nv_bfloat16 l0 = __float2bfloat16(w0 - __bfloat162float(h0));
    __nv_bfloat16 l1 = __float2bfloat16(w1 - __bfloat162float(h1));
    int kt = kp >> 3, kpl = kp & 7;
    int pos = 2 * (kpl & 3) + (kpl >> 2);
    uint32_t base = (uint32_t)((l * 32 + kt) * 2) * 4096u + (uint32_t)(n * 8 + pos);
    gW[base]        = (uint32_t)__bfloat16_as_ushort(h0) | ((uint32_t)__bfloat16_as_ushort(h1) << 16);
    gW[base + 4096] = (uint32_t)__bfloat16_as_ushort(l0) | ((uint32_t)__bfloat16_as_ushort(l1) << 16);
}

// ---------------- layer 0 (K = 6) ----------------
template<int HOUT>
__device__ __noinline__ void layer0(uint8_t* sm,
    const float* __restrict__ inputs, const float* __restrict__ W_in,
    const float* __restrict__ b_in, const float* __restrict__ lnw,
    const float* __restrict__ lnb, int rowbase)
{
    uint32_t* actHi = (uint32_t*)(sm + SM_ACT_HI);
    uint32_t* actLo = (uint32_t*)(sm + SM_ACT_LO);
    float* xin   = (float*)(sm + SM_XIN);
    float* sW    = (float*)(sm + SM_L0W);
    float* sBias = (float*)(sm + SM_L0B);
    float* sLw   = (float*)(sm + SM_L0LW);
    float* sLb   = (float*)(sm + SM_L0LB);
    const int tid = threadIdx.x;

    for (int i = tid; i < HOUT * 6; i += NTHR) sW[i] = W_in[i];
    for (int i = tid; i < HOUT; i += NTHR) { sBias[i] = b_in[i]; sLw[i] = lnw[i]; sLb[i] = lnb[i]; }
    for (int i = tid; i < TMR * 6; i += NTHR) xin[i] = inputs[rowbase * 6 + i];
    __syncthreads();

    const int row = tid >> 3, sub = (tid >> 2) & 1, cp = tid & 3;
    float x[6];
    #pragma unroll
    for (int k = 0; k < 6; ++k) x[k] = xin[row * 6 + k];

    float s = 0.f, q = 0.f;
    for (int nt = sub; nt < HOUT / 8; nt += 2) {
        #pragma unroll
        for (int e = 0; e < 2; ++e) {
            int col = 8 * nt + 2 * cp + e;
            const float* w = sW + col * 6;
            float v = sBias[col];
            #pragma unroll
            for (int k = 0; k < 6; ++k) v += x[k] * w[k];
            s += v; q += v * v;
        }
    }
    #pragma unroll
    for (int o = 1; o <= 4; o <<= 1) {
        s += __shfl_xor_sync(0xffffffffu, s, o);
        q += __shfl_xor_sync(0xffffffffu, q, o);
    }
    const float mean = s * (1.0f / HOUT);
    const float rstd = rsqrtf(q * (1.0f / HOUT) - mean * mean + 1e-5f);

    for (int nt = sub; nt < HOUT / 8; nt += 2) {
        float y[2];
        #pragma unroll
        for (int e = 0; e < 2; ++e) {
            int col = 8 * nt + 2 * cp + e;
            const float* w = sW + col * 6;
            float v = sBias[col];
            #pragma unroll
            for (int k = 0; k < 6; ++k) v += x[k] * w[k];
            y[e] = fmaxf((v - mean) * rstd * sLw[col] + sLb[col], 0.f);
        }
        uint32_t lo;
        uint32_t hi = pack_split(y[0], y[1], lo);
        uint32_t idx = (uint32_t)(nt * TMR + row) * 4u + (uint32_t)cp;
        actHi[idx] = hi; actLo[idx] = lo;
    }
    __syncthreads();
}

// ---- mid layer: k16 HMMA 3-split GEMM, warp-private ring, cross-layer prefetch ----
// NT2 = next layer's n8-tiles per warp (0 = no prefetch).  PF = units 0,1 were
// already staged by the previous layer's tail prefetch.
template<int HIN, int HOUT, bool LAST, int NT2, bool PF>
__device__ __noinline__ void mid_layer(uint8_t* sm, int lane, int w,
    int lidx, int nlidx, int fidx,
    const float* __restrict__ bias, const float* __restrict__ lnw,
    const float* __restrict__ lnb, const float* __restrict__ W_out,
    const float* __restrict__ b_out, float* __restrict__ out, int rowbase)
{
    constexpr int KT  = HIN / 16;          // k16 chunks
    constexpr int NU  = 2 * KT;            // plane units
    constexpr int NT  = HOUT / 64;         // n8-tiles per warp
    constexpr int NJ  = NT / 2;            // cp16 per lane per plane slice

    uint32_t* actHi = (uint32_t*)(sm + SM_ACT_HI);
    uint32_t* actLo = (uint32_t*)(sm + SM_ACT_LO);
    uint32_t* wbuf  = (uint32_t*)(sm + SM_WBUF);
    float* red    = (float*)(sm + SM_RED);
    float* outAcc = (float*)(sm + SM_OUTACC);
    const int tid = threadIdx.x;

    const int r  = lane >> 2;
    const int cp = lane & 3;
    const int ntb = w * NT;
    const uint32_t boff = (uint32_t)(r * 8 + 2 * cp);

    // warp-private 3-buffer ring, 512 words per buffer
    uint32_t* wb = wbuf + w * 1536;
    const uint32_t* wsl = gW + (uint32_t)lidx * 262144u + (uint32_t)ntb * 64u + (uint32_t)(lane * 4);

    auto stageu = [&](int u, int b) {
        const uint32_t* src = wsl + (uint32_t)u * 4096u;
        uint32_t* dst = wb + b * 512 + lane * 4;
        #pragma unroll
        for (int j = 0; j < NJ; ++j)
            cp16(dst + j * 128, src + j * 128);
        cp_commit();
    };

    float acc[2][NT][4];
    #pragma unroll
    for (int mb = 0; mb < 2; ++mb)
        #pragma unroll
        for (int t = 0; t < NT; ++t)
            acc[mb][t][0] = acc[mb][t][1] = acc[mb][t][2] = acc[mb][t][3] = 0.f;

    uint32_t ah[2][4];   // hi A-frags persist from hi-unit to lo-unit

    if (!PF) {           // predecessor did not prefetch: stage units 0,1 now
        stageu(0, 0);
        stageu(1, 1);
    }

    int b = 0;
    #pragma unroll 2
    for (int u = 0; u < NU; ++u) {
        if (u + 1 < NU) cp_wait1(); else cp_wait0();
        __syncwarp();
        if (u + 2 < NU) {
            int b2 = b + 2; if (b2 >= 3) b2 -= 3;
            stageu(u + 2, b2);
        }

        const uint32_t* B = wb + b * 512;
        const int kt = u >> 1;

        if ((u & 1) == 0) {
            uint32_t al[2][4];
            #pragma unroll
            for (int mb = 0; mb < 2; ++mb) {
                uint32_t i0 = (uint32_t)((2 * kt) * TMR + mb * 16 + r) * 4u + cp;
                uint32_t i2 = i0 + (uint32_t)(TMR * 4);
                ah[mb][0] = actHi[i0]; ah[mb][1] = actHi[i0 + 32];
                ah[mb][2] = actHi[i2]; ah[mb][3] = actHi[i2 + 32];
                al[mb][0] = actLo[i0]; al[mb][1] = actLo[i0 + 32];
                al[mb][2] = actLo[i2]; al[mb][3] = actLo[i2 + 32];
            }
            #pragma unroll
            for (int t = 0; t < NT; ++t) {
                uint2 bh = *(const uint2*)(B + (uint32_t)t * 64u + boff);
                #pragma unroll
                for (int mb = 0; mb < 2; ++mb) {
                    mma_k16(acc[mb][t], ah[mb][0], ah[mb][1], ah[mb][2], ah[mb][3], bh.x, bh.y);
                    mma_k16(acc[mb][t], al[mb][0], al[mb][1], al[mb][2], al[mb][3], bh.x, bh.y);
                }
            }
        } else {
            #pragma unroll
            for (int t = 0; t < NT; ++t) {
                uint2 bl = *(const uint2*)(B + (uint32_t)t * 64u + boff);
                #pragma unroll
                for (int mb = 0; mb < 2; ++mb)
                    mma_k16(acc[mb][t], ah[mb][0], ah[mb][1], ah[mb][2], ah[mb][3], bl.x, bl.y);
            }
        }
        b = (b == 2) ? 0 : b + 1;
    }

    // ---- cross-layer prefetch: stage next layer's units 0,1 into buffers 0,1.
    // Warp-private; issued before the epilogue so staging hides behind LN/pack.
    if (NT2 > 0) {
        const uint32_t* wsl2 = gW + (uint32_t)nlidx * 262144u
                             + (uint32_t)(w * NT2) * 64u + (uint32_t)(lane * 4);
        #pragma unroll
        for (int un = 0; un < 2; ++un) {
            const uint32_t* src = wsl2 + (uint32_t)un * 4096u;
            uint32_t* dst = wb + un * 512 + lane * 4;
            #pragma unroll
            for (int j = 0; j < NT2 / 2; ++j)
                cp16(dst + j * 128, src + j * 128);
            cp_commit();
        }
    }

    // ---- epilogue: per-thread row slots mb*16 + r (+8) ----
    float sv[2][2], qv[2][2];
    #pragma unroll
    for (int mb = 0; mb < 2; ++mb) { sv[mb][0] = sv[mb][1] = qv[mb][0] = qv[mb][1] = 0.f; }
    #pragma unroll
    for (int t = 0; t < NT; ++t) {
        float2 bv = *(const float2*)(bias + 8 * (ntb + t) + 2 * cp);   // gmem, L2-hot
        #pragma unroll
        for (int mb = 0; mb < 2; ++mb) {
            acc[mb][t][0] += bv.x; acc[mb][t][1] += bv.y;
            acc[mb][t][2] += bv.x; acc[mb][t][3] += bv.y;
            sv[mb][0] += acc[mb][t][0] + acc[mb][t][1];
            qv[mb][0] += acc[mb][t][0] * acc[mb][t][0] + acc[mb][t][1] * acc[mb][t][1];
            sv[mb][1] += acc[mb][t][2] + acc[mb][t][3];
            qv[mb][1] += acc[mb][t][2] * acc[mb][t][2] + acc[mb][t][3] * acc[mb][t][3];
        }
    }
    #pragma unroll
    for (int o = 1; o <= 2; o <<= 1)
        #pragma unroll
        for (int mb = 0; mb < 2; ++mb)
            #pragma unroll
            for (int h = 0; h < 2; ++h) {
                sv[mb][h] += __shfl_xor_sync(0xffffffffu, sv[mb][h], o);
                qv[mb][h] += __shfl_xor_sync(0xffffffffu, qv[mb][h], o);
            }

    __syncthreads();   // ALL warps done with mainloop act reads + warp7 buf2 -> red safe

    if (cp == 0) {
        #pragma unroll
        for (int mb = 0; mb < 2; ++mb)
            #pragma unroll
            for (int h = 0; h < 2; ++h) {
                int row = mb * 16 + r + 8 * h;
                red[(w * 32 + row) * 2 + 0] = sv[mb][h];
                red[(w * 32 + row) * 2 + 1] = qv[mb][h];
            }
    }
    __syncthreads();

    float mean_[2][2], rstd_[2][2];
    #pragma unroll
    for (int mb = 0; mb < 2; ++mb)
        #pragma unroll
        for (int h = 0; h < 2; ++h) {
            int row = mb * 16 + r + 8 * h;
            float S = 0.f, Q = 0.f;
            #pragma unroll
            for (int g = 0; g < 8; ++g) {
                float2 e = *(const float2*)(red + (g * 32 + row) * 2);
                S += e.x; Q += e.y;
            }
            float m = S * (1.0f / HOUT);
            mean_[mb][h] = m;
            rstd_[mb][h] = rsqrtf(Q * (1.0f / HOUT) - m * m + 1e-5f);
        }

    if (!LAST) {
        #pragma unroll
        for (int t = 0; t < NT; ++t) {
            int col0 = 8 * (ntb + t) + 2 * cp;
            float2 lwv = *(const float2*)(lnw + col0);
            float2 lbv = *(const float2*)(lnb + col0);
            #pragma unroll
            for (int mb = 0; mb < 2; ++mb) {
                float y00 = fmaxf((acc[mb][t][0] - mean_[mb][0]) * rstd_[mb][0] * lwv.x + lbv.x, 0.f);
                float y01 = fmaxf((acc[mb][t][1] - mean_[mb][0]) * rstd_[mb][0] * lwv.y + lbv.y, 0.f);
                float y10 = fmaxf((acc[mb][t][2] - mean_[mb][1]) * rstd_[mb][1] * lwv.x + lbv.x, 0.f);
                float y11 = fmaxf((acc[mb][t][3] - mean_[mb][1]) * rstd_[mb][1] * lwv.y + lbv.y, 0.f);
                uint32_t lo0, lo1;
                uint32_t hi0 = pack_split(y00, y01, lo0);
                uint32_t hi1 = pack_split(y10, y11, lo1);
                uint32_t idx0 = (uint32_t)((ntb + t) * TMR + mb * 16 + r) * 4u + cp;
                actHi[idx0] = hi0;      actLo[idx0] = lo0;
                actHi[idx0 + 32] = hi1; actLo[idx0 + 32] = lo1;
            }
        }
        __syncthreads();
    } else {
        float p[2][2][3];
        #pragma unroll
        for (int mb = 0; mb < 2; ++mb)
            #pragma unroll
            for (int h = 0; h < 2; ++h)
                p[mb][h][0] = p[mb][h][1] = p[mb][h][2] = 0.f;
        #pragma unroll
        for (int t = 0; t < NT; ++t) {
            int col0 = 8 * (ntb + t) + 2 * cp;
            float2 lwv = *(const float2*)(lnw + col0);
            float2 lbv = *(const float2*)(lnb + col0);
            float2 wo[3];
            #pragma unroll
            for (int o = 0; o < 3; ++o) wo[o] = *(const float2*)(W_out + o * 512 + col0);
            #pragma unroll
            for (int mb = 0; mb < 2; ++mb) {
                float y00 = fmaxf((acc[mb][t][0] - mean_[mb][0]) * rstd_[mb][0] * lwv.x + lbv.x, 0.f);
                float y01 = fmaxf((acc[mb][t][1] - mean_[mb][0]) * rstd_[mb][0] * lwv.y + lbv.y, 0.f);
                float y10 = fmaxf((acc[mb][t][2] - mean_[mb][1]) * rstd_[mb][1] * lwv.x + lbv.x, 0.f);
                float y11 = fmaxf((acc[mb][t][3] - mean_[mb][1]) * rstd_[mb][1] * lwv.y + lbv.y, 0.f);
                #pragma unroll
                for (int o = 0; o < 3; ++o) {
                    p[mb][0][o] += y00 * wo[o].x + y01 * wo[o].y;
                    p[mb][1][o] += y10 * wo[o].x + y11 * wo[o].y;
                }
            }
        }
        #pragma unroll
        for (int o = 0; o < 3; ++o)
            #pragma unroll
            for (int mb = 0; mb < 2; ++mb)
                #pragma unroll
                for (int h = 0; h < 2; ++h) {
                    p[mb][h][o] += __shfl_xor_sync(0xffffffffu, p[mb][h][o], 1);
                    p[mb][h][o] += __shfl_xor_sync(0xffffffffu, p[mb][h][o], 2);
                }
        if (cp == 0) {
            #pragma unroll
            for (int mb = 0; mb < 2; ++mb)
                #pragma unroll
                for (int h = 0; h < 2; ++h) {
                    int row = mb * 16 + r + 8 * h;
                    #pragma unroll
                    for (int o = 0; o < 3; ++o)
                        outAcc[(w * 32 + row) * 3 + o] = p[mb][h][o];
                }
        }
        __syncthreads();
        if (tid < 96) {
            int row = tid / 3, o = tid - row * 3;
            float v = b_out[o];
            #pragma unroll
            for (int g = 0; g < 8; ++g) v += outAcc[(g * 32 + row) * 3 + o];
            out[(size_t)(rowbase + row) * 9 + fidx * 3 + o] = v;
        }
    }
}

// ---------------- fused kernel per factor ----------------
template<int F>
__global__ void __launch_bounds__(NTHR, 2) mipnet_tc(
    const float* __restrict__ inputs,
    const float* __restrict__ W_in, const float* __restrict__ b_in,
    const float* __restrict__ bs,
    const float* __restrict__ ln_w, const float* __restrict__ ln_b,
    const float* __restrict__ W_out, const float* __restrict__ b_out,
    float* __restrict__ out)
{
    extern __shared__ uint8_t sm[];
    const int tid  = threadIdx.x;
    const int lane = tid & 31;
    const int w    = tid >> 5;    // warp = column eighth, all 32 rows
    const int rowbase = blockIdx.x * TMR;

    constexpr int N1 = hdim<F>(1) / 64, N2 = hdim<F>(2) / 64, N3 = hdim<F>(3) / 64;
    constexpr int N4 = hdim<F>(4) / 64, N5 = hdim<F>(5) / 64, N6 = hdim<F>(6) / 64;

    layer0<hdim<F>(0)>(sm, inputs, W_in, b_in, ln_w, ln_b, rowbase);
    mid_layer<hdim<F>(0), hdim<F>(1), false, N2, false>(sm, lane, w, 0, 1, F, bs,
        ln_w + 512,  ln_b + 512,  W_out, b_out, out, rowbase);
    mid_layer<hdim<F>(1), hdim<F>(2), false, N3, true >(sm, lane, w, 1, 2, F, bs + 512,
        ln_w + 1024, ln_b + 1024, W_out, b_out, out, rowbase);
    mid_layer<hdim<F>(2), hdim<F>(3), false, N4, true >(sm, lane, w, 2, 3, F, bs + 1024,
        ln_w + 1536, ln_b + 1536, W_out, b_out, out, rowbase);
    mid_layer<hdim<F>(3), hdim<F>(4), false, N5, true >(sm, lane, w, 3, 4, F, bs + 1536,
        ln_w + 2048, ln_b + 2048, W_out, b_out, out, rowbase);
    mid_layer<hdim<F>(4), hdim<F>(5), false, N6, true >(sm, lane, w, 4, 5, F, bs + 2048,
        ln_w + 2560, ln_b + 2560, W_out, b_out, out, rowbase);
    mid_layer<hdim<F>(5), hdim<F>(6), true,  0,  true >(sm, lane, w, 5, 0, F, bs + 2560,
        ln_w + 3072, ln_b + 3072, W_out, b_out, out, rowbase);
}

extern "C" void kernel_launch(void* const* d_in, const int* in_sizes, int n_in,
                              void* d_out, int out_size) {
    const float* inputs = (const float*)d_in[0];
    const float* W_in   = (const float*)d_in[1];
    const float* b_in   = (const float*)d_in[2];
    const float* Ws     = (const float*)d_in[3];
    const float* bs     = (const float*)d_in[4];
    const float* ln_w   = (const float*)d_in[5];
    const float* ln_b   = (const float*)d_in[6];
    const float* W_out  = (const float*)d_in[7];
    const float* b_out  = (const float*)d_in[8];
    float* out = (float*)d_out;

    const int Nrows = in_sizes[0] / 6;
    const int tiles = Nrows / TMR;      // 4096

    cudaFuncSetAttribute(mipnet_tc<0>, cudaFuncAttributeMaxDynamicSharedMemorySize, SM_TOTAL);
    cudaFuncSetAttribute(mipnet_tc<1>, cudaFuncAttributeMaxDynamicSharedMemorySize, SM_TOTAL);
    cudaFuncSetAttribute(mipnet_tc<2>, cudaFuncAttributeMaxDynamicSharedMemorySize, SM_TOTAL);

    split_weights<<<3072, 256>>>(Ws);

    mipnet_tc<0><<<tiles, NTHR, SM_TOTAL>>>(inputs, W_in, b_in, bs, ln_w, ln_b, W_out, b_out, out);
    mipnet_tc<1><<<tiles, NTHR, SM_TOTAL>>>(inputs, W_in, b_in, bs, ln_w, ln_b, W_out, b_out, out);
    mipnet_tc<2><<<tiles, NTHR, SM_TOTAL>>>(inputs, W_in, b_in, bs, ln_w, ln_b, W_out, b_out, out);
}

// round 17
// speedup vs baseline: 1.2997x; 1.0302x over previous
#include <cuda_runtime.h>
#include <cuda_bf16.h>
#include <cstdint>

#define NTHR 256
#define TMR  32

// Weight blob (k16 layout): per layer 32 k16-chunks x [hl][n][pos].
// word(l, kt, hl, n, pos) at (l*32+kt)*8192 + hl*4096 + n*8 + pos,
// pos = 2*(kpl&3) + (kpl>>2) for k-pair kpl (0..7): B-fragment pair (kpl, kpl+4)
// is one contiguous 8B load: uint2 at  nt*64 + (lane>>2)*8 + 2*(lane&3).
// Plane units are contiguous: unit u = (kt*2+hl) lives at  u*4096 words.
__device__ __align__(16) uint32_t gW[6u * 262144u];   // 6 MB

// ---- smem byte offsets ----
#define SM_ACT_HI 0         // 8192 words (32 rows x 512 cols bf16-pairs)
#define SM_ACT_LO 32768     // 8192 words
#define SM_WBUF   65536     // 48 KB: per-warp 3-buffer ring (8 warps x 3 x 512 words)
#define SM_TOTAL  114688    // 112 KB -> 2 CTAs/SM
// layer0-only overlays inside WBUF (ring dead, barrier-protected):
#define SM_XIN    SM_WBUF             // layer0 input staging (768 B)
#define SM_L0W    (SM_WBUF + 1024)    // layer0 W_in (<=12 KB)
#define SM_L0B    (SM_WBUF + 16384)   // layer0 bias (2 KB)
#define SM_L0LW   (SM_WBUF + 18432)   // layer0 ln_w (2 KB)
#define SM_L0LB   (SM_WBUF + 20480)   // layer0 ln_b (2 KB)
// Epilogue scratch lives in each warp's OWN ring buffer 2 (wb + 1024 words):
//   red slice  (32 rows x 2 f = 256 B) at +0
//   outAcc     (32 rows x 3 f = 384 B) at +64 words   [LAST only]
// Buffer 2 is dead for a warp once its own mainloop finishes, and cross-layer
// prefetch touches only buffers 0/1, so no barrier is needed before writing.

__device__ __forceinline__ void cp16(void* dst, const void* src) {
    unsigned s = (unsigned)__cvta_generic_to_shared(dst);
    asm volatile("cp.async.cg.shared.global [%0], [%1], 16;" :: "r"(s), "l"(src));
}
__device__ __forceinline__ void cp_commit() { asm volatile("cp.async.commit_group;"); }
__device__ __forceinline__ void cp_wait0()  { asm volatile("cp.async.wait_group 0;"); }
__device__ __forceinline__ void cp_wait1()  { asm volatile("cp.async.wait_group 1;"); }

__device__ __forceinline__ void mma_k16(float* d,
                                        uint32_t a0, uint32_t a1, uint32_t a2, uint32_t a3,
                                        uint32_t b0, uint32_t b1) {
    asm volatile("mma.sync.aligned.m16n8k16.row.col.f32.bf16.bf16.f32 "
        "{%0,%1,%2,%3}, {%4,%5,%6,%7}, {%8,%9}, {%0,%1,%2,%3};"
        : "+f"(d[0]), "+f"(d[1]), "+f"(d[2]), "+f"(d[3])
        : "r"(a0), "r"(a1), "r"(a2), "r"(a3), "r"(b0), "r"(b1));
}

// Truncation split: hi = top 16 bits of fp32 (1 PRMT for the pair, no cvt);
// lo = rn-bf16 of the residual (one packed cvt). |lo err| <= 2^-17 |x|.
__device__ __forceinline__ uint32_t pack_split(float a, float b, uint32_t& lo) {
    uint32_t ua = __float_as_uint(a), ub = __float_as_uint(b);
    uint32_t hi;
    asm("prmt.b32 %0, %1, %2, 0x7632;" : "=r"(hi) : "r"(ua), "r"(ub));
    float ra = a - __uint_as_float(ua & 0xffff0000u);
    float rb = b - __uint_as_float(ub & 0xffff0000u);
    __nv_bfloat162 l2 = __floats2bfloat162_rn(ra, rb);
    lo = *reinterpret_cast<uint32_t*>(&l2);
    return hi;
}

template<int F>
__host__ __device__ constexpr int hdim(int l) {
    return (F == 0) ? 256 : ((F == 2) ? 512 : ((l % 2 == 0) ? 512 : 256));
}

// ---------------- prep: split fp32 weights into hi/lo bf16 blob (k16 layout) ----
__global__ void split_weights(const float* __restrict__ Ws) {
    int id = blockIdx.x * 256 + threadIdx.x;        // 6*512*256 k-pairs
    int l  = id / (512 * 256);
    int r  = id - l * (512 * 256);
    int n  = r >> 8;
    int kp = r & 255;
    const float* W = Ws + ((size_t)l * 512 + n) * 512;
    float w0 = W[2 * kp], w1 = W[2 * kp + 1];
    uint32_t lo;
    uint32_t hi = pack_split(w0, w1, lo);
    int kt = kp >> 3, kpl = kp & 7;
    int pos = 2 * (kpl & 3) + (kpl >> 2);
    uint32_t base = (uint32_t)((l * 32 + kt) * 2) * 4096u + (uint32_t)(n * 8 + pos);
    gW[base]        = hi;
    gW[base + 4096] = lo;
}

// ---------------- layer 0 (K = 6) ----------------
template<int HOUT>
__device__ __noinline__ void layer0(uint8_t* sm,
    const float* __restrict__ inputs, const float* __restrict__ W_in,
    const float* __restrict__ b_in, const float* __restrict__ lnw,
    const float* __restrict__ lnb, int rowbase)
{
    uint32_t* actHi = (uint32_t*)(sm + SM_ACT_HI);
    uint32_t* actLo = (uint32_t*)(sm + SM_ACT_LO);
    float* xin   = (float*)(sm + SM_XIN);
    float* sW    = (float*)(sm + SM_L0W);
    float* sBias = (float*)(sm + SM_L0B);
    float* sLw   = (float*)(sm + SM_L0LW);
    float* sLb   = (float*)(sm + SM_L0LB);
    const int tid = threadIdx.x;

    for (int i = tid; i < HOUT * 6; i += NTHR) sW[i] = W_in[i];
    for (int i = tid; i < HOUT; i += NTHR) { sBias[i] = b_in[i]; sLw[i] = lnw[i]; sLb[i] = lnb[i]; }
    for (int i = tid; i < TMR * 6; i += NTHR) xin[i] = inputs[rowbase * 6 + i];
    __syncthreads();

    const int row = tid >> 3, sub = (tid >> 2) & 1, cp = tid & 3;
    float x[6];
    #pragma unroll
    for (int k = 0; k < 6; ++k) x[k] = xin[row * 6 + k];

    float s = 0.f, q = 0.f;
    for (int nt = sub; nt < HOUT / 8; nt += 2) {
        #pragma unroll
        for (int e = 0; e < 2; ++e) {
            int col = 8 * nt + 2 * cp + e;
            const float* w = sW + col * 6;
            float v = sBias[col];
            #pragma unroll
            for (int k = 0; k < 6; ++k) v += x[k] * w[k];
            s += v; q += v * v;
        }
    }
    #pragma unroll
    for (int o = 1; o <= 4; o <<= 1) {
        s += __shfl_xor_sync(0xffffffffu, s, o);
        q += __shfl_xor_sync(0xffffffffu, q, o);
    }
    const float mean = s * (1.0f / HOUT);
    const float rstd = rsqrtf(q * (1.0f / HOUT) - mean * mean + 1e-5f);

    for (int nt = sub; nt < HOUT / 8; nt += 2) {
        float y[2];
        #pragma unroll
        for (int e = 0; e < 2; ++e) {
            int col = 8 * nt + 2 * cp + e;
            const float* w = sW + col * 6;
            float v = sBias[col];
            #pragma unroll
            for (int k = 0; k < 6; ++k) v += x[k] * w[k];
            y[e] = fmaxf((v - mean) * rstd * sLw[col] + sLb[col], 0.f);
        }
        uint32_t lo;
        uint32_t hi = pack_split(y[0], y[1], lo);
        uint32_t idx = (uint32_t)(nt * TMR + row) * 4u + (uint32_t)cp;
        actHi[idx] = hi; actLo[idx] = lo;
    }
    __syncthreads();
}

// ---- mid layer: k16 HMMA 3-split GEMM, warp-private ring, cross-layer prefetch ----
// NT2 = next layer's n8-tiles per warp (0 = no prefetch).  PF = units 0,1 were
// already staged by the previous layer's tail prefetch.
template<int HIN, int HOUT, bool LAST, int NT2, bool PF>
__device__ __noinline__ void mid_layer(uint8_t* sm, int lane, int w,
    int lidx, int nlidx, int fidx,
    const float* __restrict__ bias, const float* __restrict__ lnw,
    const float* __restrict__ lnb, const float* __restrict__ W_out,
    const float* __restrict__ b_out, float* __restrict__ out, int rowbase)
{
    constexpr int KT  = HIN / 16;          // k16 chunks
    constexpr int NU  = 2 * KT;            // plane units
    constexpr int NT  = HOUT / 64;         // n8-tiles per warp
    constexpr int NJ  = NT / 2;            // cp16 per lane per plane slice

    uint32_t* actHi = (uint32_t*)(sm + SM_ACT_HI);
    uint32_t* actLo = (uint32_t*)(sm + SM_ACT_LO);
    uint32_t* wbuf  = (uint32_t*)(sm + SM_WBUF);
    const int tid = threadIdx.x;

    const int r  = lane >> 2;
    const int cp = lane & 3;
    const int ntb = w * NT;
    const uint32_t boff = (uint32_t)(r * 8 + 2 * cp);

    // warp-private 3-buffer ring, 512 words per buffer
    uint32_t* wb = wbuf + w * 1536;
    const uint32_t* wsl = gW + (uint32_t)lidx * 262144u + (uint32_t)ntb * 64u + (uint32_t)(lane * 4);

    auto stageu = [&](int u, int b) {
        const uint32_t* src = wsl + (uint32_t)u * 4096u;
        uint32_t* dst = wb + b * 512 + lane * 4;
        #pragma unroll
        for (int j = 0; j < NJ; ++j)
            cp16(dst + j * 128, src + j * 128);
        cp_commit();
    };

    // acc initialized with bias (MMA accumulates on top) — epilogue bias pass deleted
    float acc[2][NT][4];
    #pragma unroll
    for (int t = 0; t < NT; ++t) {
        float2 bv = *(const float2*)(bias + 8 * (ntb + t) + 2 * cp);
        #pragma unroll
        for (int mb = 0; mb < 2; ++mb) {
            acc[mb][t][0] = bv.x; acc[mb][t][1] = bv.y;
            acc[mb][t][2] = bv.x; acc[mb][t][3] = bv.y;
        }
    }

    uint32_t ah[2][4];   // hi A-frags persist from hi-unit to lo-unit

    if (!PF) {           // predecessor did not prefetch: stage units 0,1 now
        stageu(0, 0);
        stageu(1, 1);
    }

    int b = 0;
    #pragma unroll 2
    for (int u = 0; u < NU; ++u) {
        if (u + 1 < NU) cp_wait1(); else cp_wait0();
        __syncwarp();
        if (u + 2 < NU) {
            int b2 = b + 2; if (b2 >= 3) b2 -= 3;
            stageu(u + 2, b2);
        }

        const uint32_t* B = wb + b * 512;
        const int kt = u >> 1;

        if ((u & 1) == 0) {
            uint32_t al[2][4];
            #pragma unroll
            for (int mb = 0; mb < 2; ++mb) {
                uint32_t i0 = (uint32_t)((2 * kt) * TMR + mb * 16 + r) * 4u + cp;
                uint32_t i2 = i0 + (uint32_t)(TMR * 4);
                ah[mb][0] = actHi[i0]; ah[mb][1] = actHi[i0 + 32];
                ah[mb][2] = actHi[i2]; ah[mb][3] = actHi[i2 + 32];
                al[mb][0] = actLo[i0]; al[mb][1] = actLo[i0 + 32];
                al[mb][2] = actLo[i2]; al[mb][3] = actLo[i2 + 32];
            }
            #pragma unroll
            for (int t = 0; t < NT; ++t) {
                uint2 bh = *(const uint2*)(B + (uint32_t)t * 64u + boff);
                #pragma unroll
                for (int mb = 0; mb < 2; ++mb) {
                    mma_k16(acc[mb][t], ah[mb][0], ah[mb][1], ah[mb][2], ah[mb][3], bh.x, bh.y);
                    mma_k16(acc[mb][t], al[mb][0], al[mb][1], al[mb][2], al[mb][3], bh.x, bh.y);
                }
            }
        } else {
            #pragma unroll
            for (int t = 0; t < NT; ++t) {
                uint2 bl = *(const uint2*)(B + (uint32_t)t * 64u + boff);
                #pragma unroll
                for (int mb = 0; mb < 2; ++mb)
                    mma_k16(acc[mb][t], ah[mb][0], ah[mb][1], ah[mb][2], ah[mb][3], bl.x, bl.y);
            }
        }
        b = (b == 2) ? 0 : b + 1;
    }

    // ---- cross-layer prefetch: stage next layer's units 0,1 into buffers 0,1.
    if (NT2 > 0) {
        const uint32_t* wsl2 = gW + (uint32_t)nlidx * 262144u
                             + (uint32_t)(w * NT2) * 64u + (uint32_t)(lane * 4);
        #pragma unroll
        for (int un = 0; un < 2; ++un) {
            const uint32_t* src = wsl2 + (uint32_t)un * 4096u;
            uint32_t* dst = wb + un * 512 + lane * 4;
            #pragma unroll
            for (int j = 0; j < NT2 / 2; ++j)
                cp16(dst + j * 128, src + j * 128);
            cp_commit();
        }
    }

    // ---- epilogue: per-thread row slots mb*16 + r (+8) ----
    float sv[2][2], qv[2][2];
    #pragma unroll
    for (int mb = 0; mb < 2; ++mb) { sv[mb][0] = sv[mb][1] = qv[mb][0] = qv[mb][1] = 0.f; }
    #pragma unroll
    for (int t = 0; t < NT; ++t)
        #pragma unroll
        for (int mb = 0; mb < 2; ++mb) {
            sv[mb][0] += acc[mb][t][0] + acc[mb][t][1];
            qv[mb][0] += acc[mb][t][0] * acc[mb][t][0] + acc[mb][t][1] * acc[mb][t][1];
            sv[mb][1] += acc[mb][t][2] + acc[mb][t][3];
            qv[mb][1] += acc[mb][t][2] * acc[mb][t][2] + acc[mb][t][3] * acc[mb][t][3];
        }
    #pragma unroll
    for (int o = 1; o <= 2; o <<= 1)
        #pragma unroll
        for (int mb = 0; mb < 2; ++mb)
            #pragma unroll
            for (int h = 0; h < 2; ++h) {
                sv[mb][h] += __shfl_xor_sync(0xffffffffu, sv[mb][h], o);
                qv[mb][h] += __shfl_xor_sync(0xffffffffu, qv[mb][h], o);
            }

    // write own red slice into own buffer 2 (warp-private, no barrier needed)
    float* myred = (float*)(wb + 1024);
    if (cp == 0) {
        #pragma unroll
        for (int mb = 0; mb < 2; ++mb)
            #pragma unroll
            for (int h = 0; h < 2; ++h) {
                int row = mb * 16 + r + 8 * h;
                myred[row * 2 + 0] = sv[mb][h];
                myred[row * 2 + 1] = qv[mb][h];
            }
    }
    __syncthreads();   // all warps' red slices published; all mainloop act reads done

    float mean_[2][2], rstd_[2][2];
    #pragma unroll
    for (int mb = 0; mb < 2; ++mb)
        #pragma unroll
        for (int h = 0; h < 2; ++h) {
            int row = mb * 16 + r + 8 * h;
            float S = 0.f, Q = 0.f;
            #pragma unroll
            for (int g = 0; g < 8; ++g) {
                float2 e = *(const float2*)((const float*)(wbuf + g * 1536 + 1024) + row * 2);
                S += e.x; Q += e.y;
            }
            float m = S * (1.0f / HOUT);
            mean_[mb][h] = m;
            rstd_[mb][h] = rsqrtf(Q * (1.0f / HOUT) - m * m + 1e-5f);
        }

    if (!LAST) {
        #pragma unroll
        for (int t = 0; t < NT; ++t) {
            int col0 = 8 * (ntb + t) + 2 * cp;
            float2 lwv = *(const float2*)(lnw + col0);
            float2 lbv = *(const float2*)(lnb + col0);
            #pragma unroll
            for (int mb = 0; mb < 2; ++mb) {
                float y00 = fmaxf((acc[mb][t][0] - mean_[mb][0]) * rstd_[mb][0] * lwv.x + lbv.x, 0.f);
                float y01 = fmaxf((acc[mb][t][1] - mean_[mb][0]) * rstd_[mb][0] * lwv.y + lbv.y, 0.f);
                float y10 = fmaxf((acc[mb][t][2] - mean_[mb][1]) * rstd_[mb][1] * lwv.x + lbv.x, 0.f);
                float y11 = fmaxf((acc[mb][t][3] - mean_[mb][1]) * rstd_[mb][1] * lwv.y + lbv.y, 0.f);
                uint32_t lo0, lo1;
                uint32_t hi0 = pack_split(y00, y01, lo0);
                uint32_t hi1 = pack_split(y10, y11, lo1);
                uint32_t idx0 = (uint32_t)((ntb + t) * TMR + mb * 16 + r) * 4u + cp;
                actHi[idx0] = hi0;      actLo[idx0] = lo0;
                actHi[idx0 + 32] = hi1; actLo[idx0 + 32] = lo1;
            }
        }
        __syncthreads();
    } else {
        float p[2][2][3];
        #pragma unroll
        for (int mb = 0; mb < 2; ++mb)
            #pragma unroll
            for (int h = 0; h < 2; ++h)
                p[mb][h][0] = p[mb][h][1] = p[mb][h][2] = 0.f;
        #pragma unroll
        for (int t = 0; t < NT; ++t) {
            int col0 = 8 * (ntb + t) + 2 * cp;
            float2 lwv = *(const float2*)(lnw + col0);
            float2 lbv = *(const float2*)(lnb + col0);
            float2 wo[3];
            #pragma unroll
            for (int o = 0; o < 3; ++o) wo[o] = *(const float2*)(W_out + o * 512 + col0);
            #pragma unroll
            for (int mb = 0; mb < 2; ++mb) {
                float y00 = fmaxf((acc[mb][t][0] - mean_[mb][0]) * rstd_[mb][0] * lwv.x + lbv.x, 0.f);
                float y01 = fmaxf((acc[mb][t][1] - mean_[mb][0]) * rstd_[mb][0] * lwv.y + lbv.y, 0.f);
                float y10 = fmaxf((acc[mb][t][2] - mean_[mb][1]) * rstd_[mb][1] * lwv.x + lbv.x, 0.f);
                float y11 = fmaxf((acc[mb][t][3] - mean_[mb][1]) * rstd_[mb][1] * lwv.y + lbv.y, 0.f);
                #pragma unroll
                for (int o = 0; o < 3; ++o) {
                    p[mb][0][o] += y00 * wo[o].x + y01 * wo[o].y;
                    p[mb][1][o] += y10 * wo[o].x + y11 * wo[o].y;
                }
            }
        }
        #pragma unroll
        for (int o = 0; o < 3; ++o)
            #pragma unroll
            for (int mb = 0; mb < 2; ++mb)
                #pragma unroll
                for (int h = 0; h < 2; ++h) {
                    p[mb][h][o] += __shfl_xor_sync(0xffffffffu, p[mb][h][o], 1);
                    p[mb][h][o] += __shfl_xor_sync(0xffffffffu, p[mb][h][o], 2);
                }
        // own-warp outAcc slice at buf2 + 64 words (after red slice; no clash)
        float* myout = (float*)(wb + 1024 + 64);
        if (cp == 0) {
            #pragma unroll
            for (int mb = 0; mb < 2; ++mb)
                #pragma unroll
                for (int h = 0; h < 2; ++h) {
                    int row = mb * 16 + r + 8 * h;
                    #pragma unroll
                    for (int o = 0; o < 3; ++o)
                        myout[row * 3 + o] = p[mb][h][o];
                }
        }
        __syncthreads();
        if (tid < 96) {
            int row = tid / 3, o = tid - row * 3;
            float v = b_out[o];
            #pragma unroll
            for (int g = 0; g < 8; ++g)
                v += ((const float*)(wbuf + g * 1536 + 1024 + 64))[row * 3 + o];
            out[(size_t)(rowbase + row) * 9 + fidx * 3 + o] = v;
        }
    }
}

// ---------------- fused kernel per factor ----------------
template<int F>
__global__ void __launch_bounds__(NTHR, 2) mipnet_tc(
    const float* __restrict__ inputs,
    const float* __restrict__ W_in, const float* __restrict__ b_in,
    const float* __restrict__ bs,
    const float* __restrict__ ln_w, const float* __restrict__ ln_b,
    const float* __restrict__ W_out, const float* __restrict__ b_out,
    float* __restrict__ out)
{
    extern __shared__ uint8_t sm[];
    const int tid  = threadIdx.x;
    const int lane = tid & 31;
    const int w    = tid >> 5;    // warp = column eighth, all 32 rows
    const int rowbase = blockIdx.x * TMR;

    constexpr int N2 = hdim<F>(2) / 64, N3 = hdim<F>(3) / 64;
    constexpr int N4 = hdim<F>(4) / 64, N5 = hdim<F>(5) / 64, N6 = hdim<F>(6) / 64;

    layer0<hdim<F>(0)>(sm, inputs, W_in, b_in, ln_w, ln_b, rowbase);
    mid_layer<hdim<F>(0), hdim<F>(1), false, N2, false>(sm, lane, w, 0, 1, F, bs,
        ln_w + 512,  ln_b + 512,  W_out, b_out, out, rowbase);
    mid_layer<hdim<F>(1), hdim<F>(2), false, N3, true >(sm, lane, w, 1, 2, F, bs + 512,
        ln_w + 1024, ln_b + 1024, W_out, b_out, out, rowbase);
    mid_layer<hdim<F>(2), hdim<F>(3), false, N4, true >(sm, lane, w, 2, 3, F, bs + 1024,
        ln_w + 1536, ln_b + 1536, W_out, b_out, out, rowbase);
    mid_layer<hdim<F>(3), hdim<F>(4), false, N5, true >(sm, lane, w, 3, 4, F, bs + 1536,
        ln_w + 2048, ln_b + 2048, W_out, b_out, out, rowbase);
    mid_layer<hdim<F>(4), hdim<F>(5), false, N6, true >(sm, lane, w, 4, 5, F, bs + 2048,
        ln_w + 2560, ln_b + 2560, W_out, b_out, out, rowbase);
    mid_layer<hdim<F>(5), hdim<F>(6), true,  0,  true >(sm, lane, w, 5, 0, F, bs + 2560,
        ln_w + 3072, ln_b + 3072, W_out, b_out, out, rowbase);
}

extern "C" void kernel_launch(void* const* d_in, const int* in_sizes, int n_in,
                              void* d_out, int out_size) {
    const float* inputs = (const float*)d_in[0];
    const float* W_in   = (const float*)d_in[1];
    const float* b_in   = (const float*)d_in[2];
    const float* Ws     = (const float*)d_in[3];
    const float* bs     = (const float*)d_in[4];
    const float* ln_w   = (const float*)d_in[5];
    const float* ln_b   = (const float*)d_in[6];
    const float* W_out  = (const float*)d_in[7];
    const float* b_out  = (const float*)d_in[8];
    float* out = (float*)d_out;

    const int Nrows = in_sizes[0] / 6;
    const int tiles = Nrows / TMR;      // 4096

    cudaFuncSetAttribute(mipnet_tc<0>, cudaFuncAttributeMaxDynamicSharedMemorySize, SM_TOTAL);
    cudaFuncSetAttribute(mipnet_tc<1>, cudaFuncAttributeMaxDynamicSharedMemorySize, SM_TOTAL);
    cudaFuncSetAttribute(mipnet_tc<2>, cudaFuncAttributeMaxDynamicSharedMemorySize, SM_TOTAL);

    split_weights<<<3072, 256>>>(Ws);

    mipnet_tc<0><<<tiles, NTHR, SM_TOTAL>>>(inputs, W_in, b_in, bs, ln_w, ln_b, W_out, b_out, out);
    mipnet_tc<1><<<tiles, NTHR, SM_TOTAL>>>(inputs, W_in, b_in, bs, ln_w, ln_b, W_out, b_out, out);
    mipnet_tc<2><<<tiles, NTHR, SM_TOTAL>>>(inputs, W_in, b_in, bs, ln_w, ln_b, W_out, b_out, out);
}